// round 5
// baseline (speedup 1.0000x reference)
#include <cuda_runtime.h>
#include <math.h>

#define N_NODES 100000
#define N_EDGES 1600000
#define DIM 128
#define OUTC 16

// Scratch as float4 arrays: guarantees 16B alignment for vector access.
__device__ float4 g_agg[(size_t)N_NODES * DIM / 4];
__device__ float4 g_h0 [(size_t)N_NODES * DIM / 4];
__device__ float4 g_h1 [(size_t)N_NODES * DIM / 4];

// ---------------------------------------------------------------------------
// Zero a float4 buffer (grid-stride)
// ---------------------------------------------------------------------------
__global__ void zero_kernel(float4* __restrict__ p, int n4) {
    float4 z = make_float4(0.f, 0.f, 0.f, 0.f);
    for (int i = blockIdx.x * blockDim.x + threadIdx.x; i < n4;
         i += gridDim.x * blockDim.x)
        p[i] = z;
}

// ---------------------------------------------------------------------------
// Scatter: agg[dst] += w * x[src]   (one warp per edge, float4 per lane)
// Vectorized L2 reduction (red.global.add.v4.f32, sm_90+).
// Edge indices are int32 (harness converts int64 inputs to int32).
// ---------------------------------------------------------------------------
__global__ void scatter_kernel(const float4* __restrict__ x4,
                               const int* __restrict__ src,
                               const int* __restrict__ dst,
                               const float* __restrict__ ew,
                               float4* __restrict__ agg4,
                               int use_w) {
    long long t = (long long)blockIdx.x * blockDim.x + threadIdx.x;
    int e = (int)(t >> 5);
    if (e >= N_EDGES) return;
    int lane = (int)(t & 31);

    int s = src[e];
    int d = dst[e];
    float w = use_w ? ew[e] : 1.0f;

    float4 v = x4[(size_t)s * (DIM / 4) + lane];
    v.x *= w; v.y *= w; v.z *= w; v.w *= w;

    float4* p = agg4 + (size_t)d * (DIM / 4) + lane;
    asm volatile("red.global.add.v4.f32 [%0], {%1,%2,%3,%4};"
                 :: "l"((float*)p), "f"(v.x), "f"(v.y), "f"(v.z), "f"(v.w)
                 : "memory");
}

// ---------------------------------------------------------------------------
// Fused GIN layer (128 -> 128):
//   h = (1+eps)*x + agg;  y = relu(h @ W + b);  out = y / max(||y||_2, 1e-12)
// Persistent blocks, W cached in SMEM (scalar GMEM loads: alignment-safe).
// 128 threads: thread t owns output column t for 16 nodes per tile.
// ---------------------------------------------------------------------------
__global__ void layer_kernel(const float4* __restrict__ x4,
                             const float4* __restrict__ agg4,
                             const float* __restrict__ W,
                             const float* __restrict__ b,
                             const float* __restrict__ eps,
                             float4* __restrict__ out4) {
    extern __shared__ float sm[];         // dynamic smem: 16B-aligned base
    float* sW = sm;                       // 128*128
    float* sH = sm + DIM * DIM;           // 16*128
    float* sR = sH + 16 * DIM;            // 4 warps * 16 nodes

    const int t    = threadIdx.x;         // 0..127
    const int lane = t & 31;
    const int warp = t >> 5;

    for (int i = t; i < DIM * DIM; i += 128)
        sW[i] = W[i];

    const float ep   = 1.0f + eps[0];
    const float bias = b[t];

    const int ntiles = N_NODES / 16;      // 6250 exact
    for (int tile = blockIdx.x; tile < ntiles; tile += gridDim.x) {
        const int n0 = tile * 16;
        __syncthreads();                  // protect sH / sR reuse

        for (int i = t; i < 16 * DIM / 4; i += 128) {
            float4 xv = x4  [(size_t)n0 * (DIM / 4) + i];
            float4 av = agg4[(size_t)n0 * (DIM / 4) + i];
            xv.x = ep * xv.x + av.x;
            xv.y = ep * xv.y + av.y;
            xv.z = ep * xv.z + av.z;
            xv.w = ep * xv.w + av.w;
            reinterpret_cast<float4*>(sH)[i] = xv;
        }
        __syncthreads();

        float acc[16];
#pragma unroll
        for (int i = 0; i < 16; i++) acc[i] = 0.f;

#pragma unroll 8
        for (int kc = 0; kc < 32; kc++) {
            const int k = kc * 4;
            const float w0 = sW[(k + 0) * DIM + t];
            const float w1 = sW[(k + 1) * DIM + t];
            const float w2 = sW[(k + 2) * DIM + t];
            const float w3 = sW[(k + 3) * DIM + t];
#pragma unroll
            for (int i = 0; i < 16; i++) {
                float4 h4 = reinterpret_cast<float4*>(sH)[i * 32 + kc];
                acc[i] += h4.x * w0 + h4.y * w1 + h4.z * w2 + h4.w * w3;
            }
        }

        float y[16];
#pragma unroll
        for (int i = 0; i < 16; i++) y[i] = fmaxf(acc[i] + bias, 0.f);

#pragma unroll
        for (int i = 0; i < 16; i++) {
            float s = y[i] * y[i];
#pragma unroll
            for (int o = 16; o > 0; o >>= 1)
                s += __shfl_xor_sync(0xffffffffu, s, o);
            if (lane == 0) sR[warp * 16 + i] = s;
        }
        __syncthreads();

#pragma unroll
        for (int i = 0; i < 16; i++) {
            float ns  = sR[i] + sR[16 + i] + sR[32 + i] + sR[48 + i];
            float inv = 1.0f / fmaxf(sqrtf(ns), 1e-12f);
            reinterpret_cast<float*>(out4)[(size_t)(n0 + i) * DIM + t] = y[i] * inv;
        }
    }
}

// ---------------------------------------------------------------------------
// Final GIN layer (128 -> 16) + softmax. One warp per node.
// ---------------------------------------------------------------------------
__global__ void final_kernel(const float4* __restrict__ x4,
                             const float4* __restrict__ agg4,
                             const float* __restrict__ W,
                             const float* __restrict__ b,
                             const float* __restrict__ eps,
                             float* __restrict__ logits,
                             float* __restrict__ probs) {
    __shared__ alignas(16) float sWt[OUTC * DIM]; // sWt[j*128+k] = W[k][j]
    __shared__ float sB[OUTC];

    const int t = threadIdx.x;
    for (int i = t; i < OUTC * DIM; i += blockDim.x) {
        int j = i / DIM, k = i % DIM;
        sWt[i] = W[k * OUTC + j];                 // scalar: alignment-safe
    }
    if (t < OUTC) sB[t] = b[t];
    __syncthreads();

    const float ep = 1.0f + eps[0];
    const int lane = t & 31;
    const int warp = t >> 5;
    const int wpb  = blockDim.x >> 5;
    const int gw   = gridDim.x * wpb;

    for (int n = blockIdx.x * wpb + warp; n < N_NODES; n += gw) {
        float4 xv = x4  [(size_t)n * (DIM / 4) + lane];
        float4 av = agg4[(size_t)n * (DIM / 4) + lane];
        float4 h;
        h.x = ep * xv.x + av.x;
        h.y = ep * xv.y + av.y;
        h.z = ep * xv.z + av.z;
        h.w = ep * xv.w + av.w;

        float v[OUTC];
#pragma unroll
        for (int j = 0; j < OUTC; j++) {
            float4 w4 = reinterpret_cast<float4*>(sWt + j * DIM)[lane];
            v[j] = h.x * w4.x + h.y * w4.y + h.z * w4.z + h.w * w4.w;
        }
#pragma unroll
        for (int j = 0; j < OUTC; j++) {
#pragma unroll
            for (int o = 16; o > 0; o >>= 1)
                v[j] += __shfl_xor_sync(0xffffffffu, v[j], o);
        }
        float mx = -1e30f;
#pragma unroll
        for (int j = 0; j < OUTC; j++) {
            v[j] = fmaxf(v[j] + sB[j], 0.f);
            mx = fmaxf(mx, v[j]);
        }
        float ex[OUTC];
        float se = 0.f;
#pragma unroll
        for (int j = 0; j < OUTC; j++) {
            ex[j] = expf(v[j] - mx);
            se += ex[j];
        }
        float inv = 1.f / se;
        if (lane == 0) {
#pragma unroll
            for (int j = 0; j < OUTC; j++) {
                logits[(size_t)n * OUTC + j] = v[j];
                probs [(size_t)n * OUTC + j] = ex[j] * inv;
            }
        }
    }
}

// ---------------------------------------------------------------------------
// Launch — inputs bound by SIZE (permutation-proof against metadata order).
// Expected element counts:
//   x=12,800,000  edge_index=3,200,000(int32)  edge_weight=1,600,000
//   W0/W1=16,384  W2=2,048  b0/b1=128  b2=16  eps0/1/2=1
// ---------------------------------------------------------------------------
extern "C" void kernel_launch(void* const* d_in, const int* in_sizes, int n_in,
                              void* d_out, int out_size) {
    const float* x  = nullptr;
    const int*   ei = nullptr;
    const float* ew = nullptr;
    const float* Wp[3] = {nullptr, nullptr, nullptr};
    const float* Bp[3] = {nullptr, nullptr, nullptr};
    const float* Ep[3] = {nullptr, nullptr, nullptr};
    int wi = 0, bi = 0, epi = 0;

    for (int i = 0; i < n_in; i++) {
        switch (in_sizes[i]) {
            case N_NODES * DIM:      x  = (const float*)d_in[i]; break;  // 12.8M
            case 2 * N_EDGES:        ei = (const int*)d_in[i];   break;  // 3.2M
            case N_EDGES:            ew = (const float*)d_in[i]; break;  // 1.6M
            case DIM * DIM:          if (wi < 2) Wp[wi++] = (const float*)d_in[i]; break;
            case DIM * OUTC:         Wp[2] = (const float*)d_in[i]; break;
            case DIM:                if (bi < 2) Bp[bi++] = (const float*)d_in[i]; break;
            case OUTC:               Bp[2] = (const float*)d_in[i]; break;
            case 1:                  if (epi < 3) Ep[epi++] = (const float*)d_in[i]; break;
            default: break;
        }
    }

    float* out_logits = (float*)d_out;
    float* out_probs  = out_logits + (size_t)N_NODES * OUTC;

    float4 *agg, *h0, *h1;
    cudaGetSymbolAddress((void**)&agg, g_agg);
    cudaGetSymbolAddress((void**)&h0,  g_h0);
    cudaGetSymbolAddress((void**)&h1,  g_h1);

    const int* src = ei;             // row 0
    const int* dst = ei + N_EDGES;   // row 1

    const int smem = (DIM * DIM + 16 * DIM + 64) * sizeof(float);  // ~74 KB
    cudaFuncSetAttribute(layer_kernel,
                         cudaFuncAttributeMaxDynamicSharedMemorySize, smem);

    const int zb  = 256;
    const int zn4 = N_NODES * DIM / 4;
    const int zg  = (zn4 + zb - 1) / zb;

    const int sb  = 256;
    const int sg  = (int)(((long long)N_EDGES * 32 + sb - 1) / sb);

    const float4* x4 = (const float4*)x;

    // ---- Layer 0 ----
    zero_kernel<<<zg, zb>>>(agg, zn4);
    scatter_kernel<<<sg, sb>>>(x4, src, dst, ew, agg, 1);
    layer_kernel<<<304, 128, smem>>>(x4, agg, Wp[0], Bp[0], Ep[0], h0);

    // ---- Layer 1 ----
    zero_kernel<<<zg, zb>>>(agg, zn4);
    scatter_kernel<<<sg, sb>>>(h0, src, dst, ew, agg, 1);
    layer_kernel<<<304, 128, smem>>>(h0, agg, Wp[1], Bp[1], Ep[1], h1);

    // ---- Layer 2 (no edge weight) + softmax ----
    zero_kernel<<<zg, zb>>>(agg, zn4);
    scatter_kernel<<<sg, sb>>>(h1, src, dst, ew, agg, 0);
    final_kernel<<<608, 256>>>(h1, agg, Wp[2], Bp[2], Ep[2], out_logits, out_probs);
}

// round 6
// speedup vs baseline: 1.2574x; 1.2574x over previous
#include <cuda_runtime.h>
#include <math.h>

#define N_NODES 100000
#define N_EDGES 1600000
#define DIM 128
#define OUTC 16

// ---------------------------------------------------------------------------
// Scratch (__device__ globals: allocation-free rule)
// ---------------------------------------------------------------------------
__device__ float4 g_h0[(size_t)N_NODES * DIM / 4];
__device__ float4 g_h1[(size_t)N_NODES * DIM / 4];
__device__ int    g_rowptr[N_NODES + 1];
__device__ int    g_wptr[N_NODES];          // counts, then running write ptrs
__device__ int    g_csrc[N_EDGES];          // src node per CSR slot
__device__ float  g_cw[N_EDGES];            // edge weight per CSR slot

// ---------------------------------------------------------------------------
// CSR build: zero counts -> histogram -> scan -> fill
// ---------------------------------------------------------------------------
__global__ void zero_counts_kernel(int* __restrict__ cnt) {
    int i = blockIdx.x * blockDim.x + threadIdx.x;
    if (i < N_NODES) cnt[i] = 0;
}

__global__ void hist_kernel(const int* __restrict__ dst, int* __restrict__ cnt) {
    int e = blockIdx.x * blockDim.x + threadIdx.x;
    if (e < N_EDGES) atomicAdd(&cnt[dst[e]], 1);
}

// Single-block exclusive scan over N_NODES counts (in g_wptr).
// Writes rowptr[] and resets wptr[] to the row starts for the fill pass.
__global__ void scan_kernel(int* __restrict__ cnt_and_wptr,
                            int* __restrict__ rowptr) {
    __shared__ int ssum[1024];
    const int t = threadIdx.x;
    const int per = (N_NODES + 1023) / 1024;          // 98
    const int beg = t * per;
    const int end = (beg + per < N_NODES) ? beg + per : N_NODES;

    int local[104];
    int s = 0;
    for (int i = beg; i < end; i++) { local[i - beg] = cnt_and_wptr[i]; s += local[i - beg]; }
    const int mysum = s;
    ssum[t] = s;
    __syncthreads();

    // Hillis-Steele inclusive scan over 1024 thread sums
    for (int o = 1; o < 1024; o <<= 1) {
        int v = (t >= o) ? ssum[t - o] : 0;
        __syncthreads();
        ssum[t] += v;
        __syncthreads();
    }
    int off = ssum[t] - mysum;                        // exclusive prefix

    for (int i = beg; i < end; i++) {
        rowptr[i] = off;
        cnt_and_wptr[i] = off;                        // wptr = row start
        off += local[i - beg];
    }
    if (t == 1023) rowptr[N_NODES] = N_EDGES;
}

__global__ void fill_kernel(const int* __restrict__ src,
                            const int* __restrict__ dst,
                            const float* __restrict__ ew,
                            int* __restrict__ wptr,
                            int* __restrict__ csrc,
                            float* __restrict__ cw) {
    int e = blockIdx.x * blockDim.x + threadIdx.x;
    if (e >= N_EDGES) return;
    int pos = atomicAdd(&wptr[dst[e]], 1);
    csrc[pos] = src[e];
    cw[pos]   = ew[e];
}

// ---------------------------------------------------------------------------
// Fused GIN layer (128 -> 128):
//   agg[n] = sum_{e in CSR(n)} w_e * x[src_e]      (register gather, no atomics)
//   h = (1+eps)*x + agg;  y = relu(h @ W + b);  out = y / max(||y||, 1e-12)
// Persistent blocks; W cached in SMEM. 128 thr: thread t owns out column t.
// ---------------------------------------------------------------------------
__global__ void layer_fused_kernel(const float4* __restrict__ x4,
                                   const int* __restrict__ rowptr,
                                   const int* __restrict__ csrc,
                                   const float* __restrict__ cw,
                                   const float* __restrict__ W,
                                   const float* __restrict__ b,
                                   const float* __restrict__ eps,
                                   float4* __restrict__ out4) {
    extern __shared__ float sm[];
    float* sW = sm;                       // 128*128
    float* sH = sm + DIM * DIM;           // 16*128
    float* sR = sH + 16 * DIM;            // 64

    const int t    = threadIdx.x;         // 0..127
    const int lane = t & 31;
    const int warp = t >> 5;

    for (int i = t; i < DIM * DIM; i += 128)
        sW[i] = W[i];

    const float ep   = 1.0f + eps[0];
    const float bias = b[t];

    const int ntiles = N_NODES / 16;      // 6250
    for (int tile = blockIdx.x; tile < ntiles; tile += gridDim.x) {
        const int n0 = tile * 16;
        __syncthreads();                  // sH/sR safe to overwrite

        // Gather + (1+eps)x: each warp builds 4 node rows of the h-tile
#pragma unroll
        for (int j = 0; j < 4; j++) {
            const int n   = n0 + warp * 4 + j;
            const int beg = rowptr[n];
            const int end = rowptr[n + 1];

            float4 a0 = make_float4(0.f, 0.f, 0.f, 0.f);
            float4 a1 = make_float4(0.f, 0.f, 0.f, 0.f);
            int i = beg;
            for (; i + 1 < end; i += 2) {
                int   s0 = csrc[i],   s1 = csrc[i + 1];
                float w0 = cw[i],     w1 = cw[i + 1];
                float4 v0 = x4[(size_t)s0 * (DIM / 4) + lane];
                float4 v1 = x4[(size_t)s1 * (DIM / 4) + lane];
                a0.x += w0 * v0.x; a0.y += w0 * v0.y;
                a0.z += w0 * v0.z; a0.w += w0 * v0.w;
                a1.x += w1 * v1.x; a1.y += w1 * v1.y;
                a1.z += w1 * v1.z; a1.w += w1 * v1.w;
            }
            if (i < end) {
                int s0 = csrc[i]; float w0 = cw[i];
                float4 v0 = x4[(size_t)s0 * (DIM / 4) + lane];
                a0.x += w0 * v0.x; a0.y += w0 * v0.y;
                a0.z += w0 * v0.z; a0.w += w0 * v0.w;
            }
            float4 xv = x4[(size_t)n * (DIM / 4) + lane];
            float4 h;
            h.x = ep * xv.x + a0.x + a1.x;
            h.y = ep * xv.y + a0.y + a1.y;
            h.z = ep * xv.z + a0.z + a1.z;
            h.w = ep * xv.w + a0.w + a1.w;
            reinterpret_cast<float4*>(sH)[(warp * 4 + j) * (DIM / 4) + lane] = h;
        }
        __syncthreads();

        // GEMM: acc[i] = sum_k h[i][k] * W[k][t]
        float acc[16];
#pragma unroll
        for (int i = 0; i < 16; i++) acc[i] = 0.f;

#pragma unroll 8
        for (int kc = 0; kc < 32; kc++) {
            const int k = kc * 4;
            const float w0 = sW[(k + 0) * DIM + t];
            const float w1 = sW[(k + 1) * DIM + t];
            const float w2 = sW[(k + 2) * DIM + t];
            const float w3 = sW[(k + 3) * DIM + t];
#pragma unroll
            for (int i = 0; i < 16; i++) {
                float4 h4 = reinterpret_cast<float4*>(sH)[i * 32 + kc];
                acc[i] += h4.x * w0 + h4.y * w1 + h4.z * w2 + h4.w * w3;
            }
        }

        float y[16];
#pragma unroll
        for (int i = 0; i < 16; i++) y[i] = fmaxf(acc[i] + bias, 0.f);

        // per-node L2 norm across the 128 columns
#pragma unroll
        for (int i = 0; i < 16; i++) {
            float s = y[i] * y[i];
#pragma unroll
            for (int o = 16; o > 0; o >>= 1)
                s += __shfl_xor_sync(0xffffffffu, s, o);
            if (lane == 0) sR[warp * 16 + i] = s;
        }
        __syncthreads();

#pragma unroll
        for (int i = 0; i < 16; i++) {
            float ns  = sR[i] + sR[16 + i] + sR[32 + i] + sR[48 + i];
            float inv = 1.0f / fmaxf(sqrtf(ns), 1e-12f);
            reinterpret_cast<float*>(out4)[(size_t)(n0 + i) * DIM + t] = y[i] * inv;
        }
    }
}

// ---------------------------------------------------------------------------
// Fused final layer (128 -> 16, NO edge weight) + softmax. One warp per node.
// ---------------------------------------------------------------------------
__global__ void final_fused_kernel(const float4* __restrict__ x4,
                                   const int* __restrict__ rowptr,
                                   const int* __restrict__ csrc,
                                   const float* __restrict__ W,
                                   const float* __restrict__ b,
                                   const float* __restrict__ eps,
                                   float* __restrict__ logits,
                                   float* __restrict__ probs) {
    __shared__ alignas(16) float sWt[OUTC * DIM];   // sWt[j*128+k] = W[k][j]
    __shared__ float sB[OUTC];

    const int t = threadIdx.x;
    for (int i = t; i < OUTC * DIM; i += blockDim.x) {
        int j = i / DIM, k = i % DIM;
        sWt[i] = W[k * OUTC + j];
    }
    if (t < OUTC) sB[t] = b[t];
    __syncthreads();

    const float ep = 1.0f + eps[0];
    const int lane = t & 31;
    const int warp = t >> 5;
    const int wpb  = blockDim.x >> 5;
    const int gw   = gridDim.x * wpb;

    for (int n = blockIdx.x * wpb + warp; n < N_NODES; n += gw) {
        const int beg = rowptr[n];
        const int end = rowptr[n + 1];

        float4 a0 = make_float4(0.f, 0.f, 0.f, 0.f);
        float4 a1 = make_float4(0.f, 0.f, 0.f, 0.f);
        int i = beg;
        for (; i + 1 < end; i += 2) {
            int s0 = csrc[i], s1 = csrc[i + 1];
            float4 v0 = x4[(size_t)s0 * (DIM / 4) + lane];
            float4 v1 = x4[(size_t)s1 * (DIM / 4) + lane];
            a0.x += v0.x; a0.y += v0.y; a0.z += v0.z; a0.w += v0.w;
            a1.x += v1.x; a1.y += v1.y; a1.z += v1.z; a1.w += v1.w;
        }
        if (i < end) {
            int s0 = csrc[i];
            float4 v0 = x4[(size_t)s0 * (DIM / 4) + lane];
            a0.x += v0.x; a0.y += v0.y; a0.z += v0.z; a0.w += v0.w;
        }

        float4 xv = x4[(size_t)n * (DIM / 4) + lane];
        float4 h;
        h.x = ep * xv.x + a0.x + a1.x;
        h.y = ep * xv.y + a0.y + a1.y;
        h.z = ep * xv.z + a0.z + a1.z;
        h.w = ep * xv.w + a0.w + a1.w;

        float v[OUTC];
#pragma unroll
        for (int j = 0; j < OUTC; j++) {
            float4 w4 = reinterpret_cast<float4*>(sWt + j * DIM)[lane];
            v[j] = h.x * w4.x + h.y * w4.y + h.z * w4.z + h.w * w4.w;
        }
#pragma unroll
        for (int j = 0; j < OUTC; j++) {
#pragma unroll
            for (int o = 16; o > 0; o >>= 1)
                v[j] += __shfl_xor_sync(0xffffffffu, v[j], o);
        }
        float mx = -1e30f;
#pragma unroll
        for (int j = 0; j < OUTC; j++) {
            v[j] = fmaxf(v[j] + sB[j], 0.f);
            mx = fmaxf(mx, v[j]);
        }
        float ex[OUTC];
        float se = 0.f;
#pragma unroll
        for (int j = 0; j < OUTC; j++) {
            ex[j] = expf(v[j] - mx);
            se += ex[j];
        }
        float inv = 1.f / se;
        if (lane == 0) {
#pragma unroll
            for (int j = 0; j < OUTC; j++) {
                logits[(size_t)n * OUTC + j] = v[j];
                probs [(size_t)n * OUTC + j] = ex[j] * inv;
            }
        }
    }
}

// ---------------------------------------------------------------------------
// Launch — inputs bound by SIZE (permutation-proof).
// ---------------------------------------------------------------------------
extern "C" void kernel_launch(void* const* d_in, const int* in_sizes, int n_in,
                              void* d_out, int out_size) {
    const float* x  = nullptr;
    const int*   ei = nullptr;
    const float* ew = nullptr;
    const float* Wp[3] = {nullptr, nullptr, nullptr};
    const float* Bp[3] = {nullptr, nullptr, nullptr};
    const float* Ep[3] = {nullptr, nullptr, nullptr};
    int wi = 0, bi = 0, epi = 0;

    for (int i = 0; i < n_in; i++) {
        switch (in_sizes[i]) {
            case N_NODES * DIM: x  = (const float*)d_in[i]; break;
            case 2 * N_EDGES:   ei = (const int*)d_in[i];   break;
            case N_EDGES:       ew = (const float*)d_in[i]; break;
            case DIM * DIM:     if (wi < 2) Wp[wi++] = (const float*)d_in[i]; break;
            case DIM * OUTC:    Wp[2] = (const float*)d_in[i]; break;
            case DIM:           if (bi < 2) Bp[bi++] = (const float*)d_in[i]; break;
            case OUTC:          Bp[2] = (const float*)d_in[i]; break;
            case 1:             if (epi < 3) Ep[epi++] = (const float*)d_in[i]; break;
            default: break;
        }
    }

    float* out_logits = (float*)d_out;
    float* out_probs  = out_logits + (size_t)N_NODES * OUTC;

    float4 *h0, *h1;
    int *rowptr, *wptr, *csrc;
    float *cw;
    cudaGetSymbolAddress((void**)&h0,     g_h0);
    cudaGetSymbolAddress((void**)&h1,     g_h1);
    cudaGetSymbolAddress((void**)&rowptr, g_rowptr);
    cudaGetSymbolAddress((void**)&wptr,   g_wptr);
    cudaGetSymbolAddress((void**)&csrc,   g_csrc);
    cudaGetSymbolAddress((void**)&cw,     g_cw);

    const int* src = ei;             // row 0
    const int* dst = ei + N_EDGES;   // row 1

    const int smem = (DIM * DIM + 16 * DIM + 64) * sizeof(float);  // ~74 KB
    cudaFuncSetAttribute(layer_fused_kernel,
                         cudaFuncAttributeMaxDynamicSharedMemorySize, smem);

    const float4* x4 = (const float4*)x;

    // ---- CSR build (by destination), reused for all 3 layers ----
    zero_counts_kernel<<<(N_NODES + 255) / 256, 256>>>(wptr);
    hist_kernel<<<(N_EDGES + 255) / 256, 256>>>(dst, wptr);
    scan_kernel<<<1, 1024>>>(wptr, rowptr);
    fill_kernel<<<(N_EDGES + 255) / 256, 256>>>(src, dst, ew, wptr, csrc, cw);

    // ---- Layers (fused gather + GEMM + norm) ----
    layer_fused_kernel<<<444, 128, smem>>>(x4, rowptr, csrc, cw,
                                           Wp[0], Bp[0], Ep[0], h0);
    layer_fused_kernel<<<444, 128, smem>>>(h0, rowptr, csrc, cw,
                                           Wp[1], Bp[1], Ep[1], h1);
    final_fused_kernel<<<608, 256>>>(h1, rowptr, csrc,
                                     Wp[2], Bp[2], Ep[2], out_logits, out_probs);
}